// round 2
// baseline (speedup 1.0000x reference)
#include <cuda_runtime.h>
#include <cstdint>
#include <cstddef>

#define DD 100
#define BMAX 128
#define TMAX 3008

// Scratch (static __device__ — no allocations allowed)
static __device__ float g_buf[(size_t)BMAX * TMAX * DD];   // w_r @ h per (b,t)
static __device__ float pre_buf[(size_t)BMAX * TMAX];      // content+salience+abs_pos+b
static __device__ float ds_buf[BMAX * DD];                 // d @ w_s
static __device__ float apos_buf[TMAX];                    // pos_table @ w_ap

__device__ __forceinline__ float tanh_ap(float x) {
    float y; asm("tanh.approx.f32 %0, %1;" : "=f"(y) : "f"(x)); return y;
}
__device__ __forceinline__ float rcp_ap(float x) {
    float y; asm("rcp.approx.f32 %0, %1;" : "=f"(y) : "f"(x)); return y;
}
__device__ __forceinline__ float ex2_ap(float x) {
    float y; asm("ex2.approx.f32 %0, %1;" : "=f"(y) : "f"(x)); return y;
}

// ---------------------------------------------------------------------------
// k0: ds[b,e] = sum_d d[b,d] * w_s[d,e];  apos[t] = sum_e pos[t,e]*w_ap[e]
// ---------------------------------------------------------------------------
__global__ void k0_kernel(const float* __restrict__ dvec,
                          const float* __restrict__ w_s,
                          const float* __restrict__ pos,
                          const float* __restrict__ w_ap,
                          int B, int T) {
    int blk = blockIdx.x;
    if (blk < B) {
        int e = threadIdx.x;
        if (e < DD) {
            const float* dv = dvec + blk * DD;
            float acc = 0.f;
            #pragma unroll 4
            for (int d0 = 0; d0 < DD; ++d0)
                acc = fmaf(dv[d0], w_s[d0 * DD + e], acc);
            ds_buf[blk * DD + e] = acc;
        }
    } else {
        __shared__ float wap[DD];
        if (threadIdx.x < DD) wap[threadIdx.x] = w_ap[threadIdx.x];
        __syncthreads();
        int t = (blk - B) * 128 + threadIdx.x;
        if (t < T) {
            const float* pr = pos + (size_t)t * DD;
            float acc = 0.f;
            #pragma unroll 4
            for (int e = 0; e < DD; ++e)
                acc = fmaf(pr[e], wap[e], acc);
            apos_buf[t] = acc;
        }
    }
}

// ---------------------------------------------------------------------------
// k1: out[b,t,c] = sum_e W[c,e]*h[b,t,e] for 104 cols:
//   c<100 : W[c] = w_r row c           -> g_buf
//   c=100 : w_c   (content)
//   c=101 : ds[b] (salience)           -> pre_buf = sum + apos + bias
//   c=102,103 : 0
// Two passes of 52 cols each so static SMEM stays under 48 KB (no
// cudaFuncSetAttribute needed). 64 t-rows per CTA, 208 threads, each
// thread computes a 4t x 4c block per pass.
// ---------------------------------------------------------------------------
#define TT 64
#define HSROW 68
#define WHALF 52

__global__ void __launch_bounds__(208) k1_kernel(const float* __restrict__ h,
                                                 const float* __restrict__ w_r,
                                                 const float* __restrict__ w_c,
                                                 const float* __restrict__ bscal,
                                                 int B, int T) {
    __shared__ float ws[DD * WHALF];   // [e][52]  one column-half, e-major
    __shared__ float hs[DD * HSROW];   // [e][68]  transposed h tile

    int b  = blockIdx.y;
    int t0 = blockIdx.x * TT;
    int tid = threadIdx.x;

    // Load transposed h tile once (coalesced read of h)
    const float* hb = h + ((size_t)b * T + t0) * DD;
    for (int idx = tid; idx < TT * DD; idx += 208) {
        int e = idx % DD;
        int t = idx / DD;
        float v = (t0 + t < T) ? hb[idx] : 0.f;
        hs[e * HSROW + t] = v;
    }

    int p  = tid % 13;   // float4-col index within the 52-col half
    int tg = tid / 13;   // 0..15 -> t rows 4*tg..4*tg+3

    const float4* ws4 = (const float4*)ws;   // row stride WHALF/4 = 13
    const float4* hs4 = (const float4*)hs;   // row stride HSROW/4 = 17

    float bias = bscal[0];

    #pragma unroll
    for (int pass = 0; pass < 2; ++pass) {
        int cbase = pass * WHALF;
        if (pass) __syncthreads();   // pass0 compute done before ws overwrite

        // Load this half of the extended weight matrix, transposed.
        for (int idx = tid; idx < DD * WHALF; idx += 208) {
            int e = idx % DD;
            int c = idx / DD;
            int gc = cbase + c;
            float v;
            if (gc < DD)           v = w_r[gc * DD + e];
            else if (gc == 100)    v = w_c[e];
            else if (gc == 101)    v = ds_buf[b * DD + e];
            else                   v = 0.f;
            ws[e * WHALF + c] = v;
        }
        __syncthreads();

        float4 acc[4];
        #pragma unroll
        for (int i = 0; i < 4; ++i) acc[i] = make_float4(0.f, 0.f, 0.f, 0.f);

        #pragma unroll 2
        for (int e = 0; e < DD; ++e) {
            float4 w0 = ws4[e * 13 + p];
            float4 hv = hs4[e * 17 + tg];
            #pragma unroll
            for (int i = 0; i < 4; ++i) {
                float hh = (i == 0) ? hv.x : (i == 1) ? hv.y : (i == 2) ? hv.z : hv.w;
                acc[i].x = fmaf(hh, w0.x, acc[i].x);
                acc[i].y = fmaf(hh, w0.y, acc[i].y);
                acc[i].z = fmaf(hh, w0.z, acc[i].z);
                acc[i].w = fmaf(hh, w0.w, acc[i].w);
            }
        }

        #pragma unroll
        for (int i = 0; i < 4; ++i) {
            int t = t0 + 4 * tg + i;
            if (t >= T) continue;
            int gc = cbase + 4 * p;
            if (gc < DD) {
                float* grow = g_buf + ((size_t)b * T + t) * DD;
                *(float4*)(grow + gc) = acc[i];
            } else {
                // gc==100: (content, salience, 0, 0)
                pre_buf[(size_t)b * T + t] =
                    acc[i].x + acc[i].y + apos_buf[t] + bias;
            }
        }
    }
}

// ---------------------------------------------------------------------------
// scan: one warp per batch b. Lane L owns s[4L..4L+3] (L<25).
// Per step: nov = sum_d tanh(s_d)*g_d (bfly reduce), p = sigmoid(pre-nov),
//           s += h*p (skipped at j==0 via mask folded into A at load time).
// Depth-4 register prefetch ring hides global-load latency.
// ---------------------------------------------------------------------------
__global__ void __launch_bounds__(32, 1) scan_kernel(const float* __restrict__ h,
                                                     float* __restrict__ out,
                                                     int B, int T) {
    int b = blockIdx.x;
    int L = threadIdx.x;
    bool act = (L < 25);

    const float* gb  = g_buf + (size_t)b * T * DD;
    const float* hbp = h + (size_t)b * T * DD;
    const float* pb  = pre_buf + (size_t)b * T;
    float* ob = out + (size_t)b * T;

    float4 G[4], A[4];
    float PH[4];
    const float4 z4 = make_float4(0.f, 0.f, 0.f, 0.f);

#define LDST(JJ, SLOT) do {                                              \
        int _j = (JJ);                                                   \
        if (_j < T) {                                                    \
            PH[SLOT] = pb[_j];                                           \
            if (act) {                                                   \
                G[SLOT] = *(const float4*)(gb + _j * DD + 4 * L);        \
                float4 _hv = *(const float4*)(hbp + _j * DD + 4 * L);    \
                float _c = (_j == 0) ? 0.f : 1.f;                        \
                A[SLOT] = make_float4(_c * _hv.x, _c * _hv.y,            \
                                      _c * _hv.z, _c * _hv.w);           \
            } else { G[SLOT] = z4; A[SLOT] = z4; }                       \
        } else { G[SLOT] = z4; A[SLOT] = z4; PH[SLOT] = 0.f; }           \
    } while (0)

    LDST(0, 0); LDST(1, 1); LDST(2, 2); LDST(3, 3);

    float sx = 0.f, sy = 0.f, sz = 0.f, sw = 0.f;

    #pragma unroll 4
    for (int j = 0; j < T; ++j) {
        int slot = j & 3;
        float4 g = G[slot];
        float4 a = A[slot];
        float ph = PH[slot];
        LDST(j + 4, slot);

        float ux = tanh_ap(sx), uy = tanh_ap(sy), uz = tanh_ap(sz), uw = tanh_ap(sw);
        float m0 = ux * g.x, m1 = uy * g.y;
        m0 = fmaf(uz, g.z, m0);
        m1 = fmaf(uw, g.w, m1);
        float part = m0 + m1;
        part += __shfl_xor_sync(0xffffffffu, part, 16);
        part += __shfl_xor_sync(0xffffffffu, part, 8);
        part += __shfl_xor_sync(0xffffffffu, part, 4);
        part += __shfl_xor_sync(0xffffffffu, part, 2);
        part += __shfl_xor_sync(0xffffffffu, part, 1);

        // p = sigmoid(pre - nov), accurate (ex2 + rcp, ~2^-22 rel err)
        float zz = ph - part;
        float q = ex2_ap(zz * -1.44269504f);
        float pprob = rcp_ap(1.f + q);

        sx = fmaf(a.x, pprob, sx);
        sy = fmaf(a.y, pprob, sy);
        sz = fmaf(a.z, pprob, sz);
        sw = fmaf(a.w, pprob, sw);

        if (L == 0) ob[j] = pprob;
    }
#undef LDST
}

// ---------------------------------------------------------------------------
extern "C" void kernel_launch(void* const* d_in, const int* in_sizes, int n_in,
                              void* d_out, int out_size) {
    const float* h    = (const float*)d_in[0];  // [B,T,D]
    const float* dv   = (const float*)d_in[1];  // [B,1,D]
    const float* w_c  = (const float*)d_in[2];  // [D,1]
    const float* w_s  = (const float*)d_in[3];  // [D,D]
    const float* w_r  = (const float*)d_in[4];  // [D,D]
    const float* pos  = (const float*)d_in[5];  // [3000,D]
    const float* w_ap = (const float*)d_in[6];  // [D,1]
    const float* bsc  = (const float*)d_in[7];  // [1]
    float* out = (float*)d_out;

    int B = in_sizes[1] / DD;
    int T = in_sizes[0] / (B * DD);

    // k0: ds + abs_pos
    int grid0 = B + (T + 127) / 128;
    k0_kernel<<<grid0, 128>>>(dv, w_s, pos, w_ap, B, T);

    // k1: GEMM producing g, pre  (static smem, 48.0 KB)
    dim3 grid1((T + TT - 1) / TT, B);
    k1_kernel<<<grid1, 208>>>(h, w_r, w_c, bsc, B, T);

    // scan: one warp per batch
    scan_kernel<<<B, 32>>>(h, out, B, T);
}

// round 6
// speedup vs baseline: 1.2385x; 1.2385x over previous
#include <cuda_runtime.h>
#include <cstdint>
#include <cstddef>

#define DD 100
#define GS 128          // padded g row stride (floats)
#define BMAX 128
#define TMAX 3008

// Scratch (static __device__ — no allocations allowed)
static __device__ float g_buf[(size_t)BMAX * TMAX * GS];   // w_r @ h, padded rows
static __device__ float pre_buf[(size_t)BMAX * TMAX];      // content+salience+abs_pos+b
static __device__ float ds_buf[BMAX * DD];                 // d @ w_s
static __device__ float apos_buf[TMAX];                    // pos_table @ w_ap

__device__ __forceinline__ float tanh_ap(float x) {
    float y; asm("tanh.approx.f32 %0, %1;" : "=f"(y) : "f"(x)); return y;
}
__device__ __forceinline__ float rcp_ap(float x) {
    float y; asm("rcp.approx.f32 %0, %1;" : "=f"(y) : "f"(x)); return y;
}
__device__ __forceinline__ float ex2_ap(float x) {
    float y; asm("ex2.approx.f32 %0, %1;" : "=f"(y) : "f"(x)); return y;
}

// ---------------------------------------------------------------------------
// k0: ds[b,e] = sum_d d[b,d] * w_s[d,e];  apos[t] = sum_e pos[t,e]*w_ap[e]
// ---------------------------------------------------------------------------
__global__ void k0_kernel(const float* __restrict__ dvec,
                          const float* __restrict__ w_s,
                          const float* __restrict__ pos,
                          const float* __restrict__ w_ap,
                          int B, int T) {
    int blk = blockIdx.x;
    if (blk < B) {
        int e = threadIdx.x;
        if (e < DD) {
            const float* dv = dvec + blk * DD;
            float acc = 0.f;
            #pragma unroll 4
            for (int d0 = 0; d0 < DD; ++d0)
                acc = fmaf(dv[d0], w_s[d0 * DD + e], acc);
            ds_buf[blk * DD + e] = acc;
        }
    } else {
        __shared__ float wap[DD];
        if (threadIdx.x < DD) wap[threadIdx.x] = w_ap[threadIdx.x];
        __syncthreads();
        int t = (blk - B) * 128 + threadIdx.x;
        if (t < T) {
            const float* pr = pos + (size_t)t * DD;
            float acc = 0.f;
            #pragma unroll 4
            for (int e = 0; e < DD; ++e)
                acc = fmaf(pr[e], wap[e], acc);
            apos_buf[t] = acc;
        }
    }
}

// ---------------------------------------------------------------------------
// k1: out[b,t,c] = sum_e W[c,e]*h[b,t,e] for 104 cols:
//   c<100 : W[c] = w_r row c           -> g_buf (row stride GS)
//   c=100 : w_c (content), c=101 : ds[b] (salience) -> pre_buf
//   c=102,103 : 0
// Two passes of 52 cols each; static SMEM = 48,000 B (< 48 KB, so NO
// cudaFuncSetAttribute — that call in kernel_launch kills the harness).
// 64 t-rows per CTA, 208 threads, each thread 4t x 4c per pass.
// ---------------------------------------------------------------------------
#define TT 64
#define HSROW 68
#define WHALF 52

__global__ void __launch_bounds__(208) k1_kernel(const float* __restrict__ h,
                                                 const float* __restrict__ w_r,
                                                 const float* __restrict__ w_c,
                                                 const float* __restrict__ bscal,
                                                 int B, int T) {
    __shared__ float ws[DD * WHALF];   // [e][52]  one column-half, e-major
    __shared__ float hs[DD * HSROW];   // [e][68]  transposed h tile

    int b  = blockIdx.y;
    int t0 = blockIdx.x * TT;
    int tid = threadIdx.x;

    // Load transposed h tile once (coalesced read of h)
    const float* hb = h + ((size_t)b * T + t0) * DD;
    for (int idx = tid; idx < TT * DD; idx += 208) {
        int e = idx % DD;
        int t = idx / DD;
        float v = (t0 + t < T) ? hb[idx] : 0.f;
        hs[e * HSROW + t] = v;
    }

    int p  = tid % 13;   // float4-col index within the 52-col half
    int tg = tid / 13;   // 0..15 -> t rows 4*tg..4*tg+3

    const float4* ws4 = (const float4*)ws;   // row stride WHALF/4 = 13
    const float4* hs4 = (const float4*)hs;   // row stride HSROW/4 = 17

    float bias = bscal[0];

    #pragma unroll
    for (int pass = 0; pass < 2; ++pass) {
        int cbase = pass * WHALF;
        if (pass) __syncthreads();   // pass0 compute done before ws overwrite

        // Load this half of the extended weight matrix, transposed.
        for (int idx = tid; idx < DD * WHALF; idx += 208) {
            int e = idx % DD;
            int c = idx / DD;
            int gc = cbase + c;
            float v;
            if (gc < DD)           v = w_r[gc * DD + e];
            else if (gc == 100)    v = w_c[e];
            else if (gc == 101)    v = ds_buf[b * DD + e];
            else                   v = 0.f;
            ws[e * WHALF + c] = v;
        }
        __syncthreads();

        float4 acc[4];
        #pragma unroll
        for (int i = 0; i < 4; ++i) acc[i] = make_float4(0.f, 0.f, 0.f, 0.f);

        #pragma unroll 2
        for (int e = 0; e < DD; ++e) {
            float4 w0 = ws4[e * 13 + p];
            float4 hv = hs4[e * 17 + tg];
            #pragma unroll
            for (int i = 0; i < 4; ++i) {
                float hh = (i == 0) ? hv.x : (i == 1) ? hv.y : (i == 2) ? hv.z : hv.w;
                acc[i].x = fmaf(hh, w0.x, acc[i].x);
                acc[i].y = fmaf(hh, w0.y, acc[i].y);
                acc[i].z = fmaf(hh, w0.z, acc[i].z);
                acc[i].w = fmaf(hh, w0.w, acc[i].w);
            }
        }

        #pragma unroll
        for (int i = 0; i < 4; ++i) {
            int t = t0 + 4 * tg + i;
            if (t >= T) continue;
            int gc = cbase + 4 * p;
            if (gc < DD) {
                float* grow = g_buf + ((size_t)b * T + t) * GS;
                *(float4*)(grow + gc) = acc[i];
            } else {
                // gc==100: (content, salience, 0, 0)
                pre_buf[(size_t)b * T + t] =
                    acc[i].x + acc[i].y + apos_buf[t] + bias;
            }
        }
    }
}

// ---------------------------------------------------------------------------
// scan: one warp per batch b; all 32 lanes resident (butterfly needs them).
// Lane L<25 owns dims 4L..4L+3; lanes 25..31 are zero-contributors (clamped
// address, g scaled by 0 at load). Per step:
//   nov = bfly_sum(tanh(s).g), p = sigmoid(pre - nov), s += h*p.
// j==0 peeled (s = 0 -> nov = 0).  Depth-8 branchless prefetch ring.
// ---------------------------------------------------------------------------
__global__ void __launch_bounds__(32, 1) scan_kernel(const float* __restrict__ h,
                                                     float* __restrict__ out,
                                                     int B, int T) {
    int b = blockIdx.x;
    int L = threadIdx.x;
    float actf = (L < 25) ? 1.f : 0.f;
    int offE = (L < 25) ? 4 * L : 96;     // clamped, always valid

    const float* gb  = g_buf + (size_t)b * T * GS;
    const float* hbp = h + (size_t)b * T * DD;
    const float* pb  = pre_buf + (size_t)b * T;
    float* ob = out + (size_t)b * T;

    // j = 0: s = 0 -> tanh(s) = 0 -> nov = 0; state not updated.
    {
        float z = pb[0];
        float q = ex2_ap(z * -1.44269504f);
        float p0 = rcp_ap(1.f + q);
        if (L == 0) ob[0] = p0;
    }
    if (T <= 1) return;

    float4 G[8], A[8];
    float PHC[8];

#define LD(JJ, SL) do {                                                    \
        int _jc = ((JJ) < T) ? (JJ) : (T - 1);                             \
        float4 _g = *(const float4*)(gb + (size_t)_jc * GS + offE);        \
        _g.x *= actf; _g.y *= actf; _g.z *= actf; _g.w *= actf;            \
        G[SL] = _g;                                                        \
        A[SL] = *(const float4*)(hbp + (size_t)_jc * DD + offE);           \
        PHC[SL] = pb[_jc] * -1.44269504f;                                  \
    } while (0)

    LD(1, 1); LD(2, 2); LD(3, 3); LD(4, 4);
    LD(5, 5); LD(6, 6); LD(7, 7); LD(8, 0);

    float sx = 0.f, sy = 0.f, sz = 0.f, sw = 0.f;

    #pragma unroll 8
    for (int j = 1; j < T; ++j) {
        int sl = j & 7;
        float4 g = G[sl];
        float4 a = A[sl];
        float phc = PHC[sl];
        LD(j + 8, sl);

        float ux = tanh_ap(sx), uy = tanh_ap(sy), uz = tanh_ap(sz), uw = tanh_ap(sw);
        float m0 = ux * g.x;
        float m1 = uy * g.y;
        m0 = fmaf(uz, g.z, m0);
        m1 = fmaf(uw, g.w, m1);
        float part = m0 + m1;
        part += __shfl_xor_sync(0xffffffffu, part, 16);
        part += __shfl_xor_sync(0xffffffffu, part, 8);
        part += __shfl_xor_sync(0xffffffffu, part, 4);
        part += __shfl_xor_sync(0xffffffffu, part, 2);
        part += __shfl_xor_sync(0xffffffffu, part, 1);

        // zz = -(pre - nov)*log2e = nov*log2e + phc   (phc precomputed)
        float zz = fmaf(part, 1.44269504f, phc);
        float q = ex2_ap(zz);
        float pp = rcp_ap(1.f + q);

        sx = fmaf(a.x, pp, sx);
        sy = fmaf(a.y, pp, sy);
        sz = fmaf(a.z, pp, sz);
        sw = fmaf(a.w, pp, sw);

        if (L == 0) ob[j] = pp;
    }
#undef LD
}

// ---------------------------------------------------------------------------
extern "C" void kernel_launch(void* const* d_in, const int* in_sizes, int n_in,
                              void* d_out, int out_size) {
    const float* h    = (const float*)d_in[0];  // [B,T,D]
    const float* dv   = (const float*)d_in[1];  // [B,1,D]
    const float* w_c  = (const float*)d_in[2];  // [D,1]
    const float* w_s  = (const float*)d_in[3];  // [D,D]
    const float* w_r  = (const float*)d_in[4];  // [D,D]
    const float* pos  = (const float*)d_in[5];  // [3000,D]
    const float* w_ap = (const float*)d_in[6];  // [D,1]
    const float* bsc  = (const float*)d_in[7];  // [1]
    float* out = (float*)d_out;

    int B = in_sizes[1] / DD;
    int T = in_sizes[0] / (B * DD);

    // k0: ds + abs_pos
    int grid0 = B + (T + 127) / 128;
    k0_kernel<<<grid0, 128>>>(dv, w_s, pos, w_ap, B, T);

    // k1: GEMM producing g, pre  (static SMEM 48.0 KB — no attribute calls)
    dim3 grid1((T + TT - 1) / TT, B);
    k1_kernel<<<grid1, 208>>>(h, w_r, w_c, bsc, B, T);

    // scan: one warp per batch
    scan_kernel<<<B, 32>>>(h, out, B, T);
}

// round 7
// speedup vs baseline: 1.3927x; 1.1245x over previous
#include <cuda_runtime.h>
#include <cstdint>
#include <cstddef>

#define DD 100
#define GS 128          // padded g row stride (floats)
#define BMAX 128
#define TMAX 3008

// Scratch (static __device__ — no allocations allowed)
static __device__ float g_buf[(size_t)BMAX * TMAX * GS];   // w_r @ h, padded rows
static __device__ float pre_buf[(size_t)BMAX * TMAX];      // content+salience+abs_pos+b
static __device__ float ds_buf[BMAX * DD];                 // d @ w_s
static __device__ float apos_buf[TMAX];                    // pos_table @ w_ap

__device__ __forceinline__ float tanh_ap(float x) {
    float y; asm("tanh.approx.f32 %0, %1;" : "=f"(y) : "f"(x)); return y;
}
__device__ __forceinline__ float rcp_ap(float x) {
    float y; asm("rcp.approx.f32 %0, %1;" : "=f"(y) : "f"(x)); return y;
}
__device__ __forceinline__ float ex2_ap(float x) {
    float y; asm("ex2.approx.f32 %0, %1;" : "=f"(y) : "f"(x)); return y;
}
__device__ __forceinline__ int redux_add_i32(int v) {
    int r;
    asm("redux.sync.add.s32 %0, %1, 0xffffffff;" : "=r"(r) : "r"(v));
    return r;
}

// ---------------------------------------------------------------------------
// k0: ds[b,e] = sum_d d[b,d] * w_s[d,e];  apos[t] = sum_e pos[t,e]*w_ap[e]
// ---------------------------------------------------------------------------
__global__ void k0_kernel(const float* __restrict__ dvec,
                          const float* __restrict__ w_s,
                          const float* __restrict__ pos,
                          const float* __restrict__ w_ap,
                          int B, int T) {
    int blk = blockIdx.x;
    if (blk < B) {
        int e = threadIdx.x;
        if (e < DD) {
            const float* dv = dvec + blk * DD;
            float acc = 0.f;
            #pragma unroll 4
            for (int d0 = 0; d0 < DD; ++d0)
                acc = fmaf(dv[d0], w_s[d0 * DD + e], acc);
            ds_buf[blk * DD + e] = acc;
        }
    } else {
        __shared__ float wap[DD];
        if (threadIdx.x < DD) wap[threadIdx.x] = w_ap[threadIdx.x];
        __syncthreads();
        int t = (blk - B) * 128 + threadIdx.x;
        if (t < T) {
            const float* pr = pos + (size_t)t * DD;
            float acc = 0.f;
            #pragma unroll 4
            for (int e = 0; e < DD; ++e)
                acc = fmaf(pr[e], wap[e], acc);
            apos_buf[t] = acc;
        }
    }
}

// ---------------------------------------------------------------------------
// k1: out[b,t,c] = sum_e W[c,e]*h[b,t,e] for 104 cols:
//   c<100 : W[c] = w_r row c           -> g_buf (row stride GS)
//   c=100 : w_c (content), c=101 : ds[b] (salience) -> pre_buf
//   c=102,103 : 0
// K-split: two passes over e (0..49, 50..99); per pass both tiles fit in
// 47,200 B static SMEM (no cudaFuncSetAttribute — that kills the harness).
// TT=128 t-rows per CTA, 208 threads, 8t x 8c register tile per thread;
// accumulators persist across e-passes. LDS at half the crossbar floor,
// FMA-bound.
// ---------------------------------------------------------------------------
#define TT 128
#define WSROW 104
#define HSROW 132      // 128 + 4 pad -> float4 row stride 33
#define EHALF 50

__global__ void __launch_bounds__(208) k1_kernel(const float* __restrict__ h,
                                                 const float* __restrict__ w_r,
                                                 const float* __restrict__ w_c,
                                                 const float* __restrict__ bscal,
                                                 int B, int T) {
    __shared__ float ws[EHALF * WSROW];   // [e2][104]  20,800 B
    __shared__ float hs[EHALF * HSROW];   // [e2][132]  26,400 B

    int b  = blockIdx.y;
    int t0 = blockIdx.x * TT;
    int tid = threadIdx.x;

    int p  = tid % 13;   // col quad index
    int tg = tid / 13;   // 0..15 -> rows 8*tg..8*tg+7

    const float4* ws4 = (const float4*)ws;   // row stride 26
    const float4* hs4 = (const float4*)hs;   // row stride 33
    const float* hb = h + ((size_t)b * T + t0) * DD;

    float4 a0[8], a1[8];
    #pragma unroll
    for (int i = 0; i < 8; ++i) {
        a0[i] = make_float4(0.f, 0.f, 0.f, 0.f);
        a1[i] = make_float4(0.f, 0.f, 0.f, 0.f);
    }

    #pragma unroll
    for (int kk = 0; kk < 2; ++kk) {
        if (kk) __syncthreads();   // pass0 compute done before overwrite
        int ebase = kk * EHALF;

        // weights half, transposed: ws[e2][c]
        for (int idx = tid; idx < EHALF * WSROW; idx += 208) {
            int e2 = idx % EHALF;
            int c  = idx / EHALF;
            int e  = ebase + e2;
            float v;
            if (c < DD)          v = w_r[c * DD + e];
            else if (c == 100)   v = w_c[e];
            else if (c == 101)   v = ds_buf[b * DD + e];
            else                 v = 0.f;
            ws[e2 * WSROW + c] = v;
        }
        // h tile half, transposed: hs[e2][t]
        for (int idx = tid; idx < TT * EHALF; idx += 208) {
            int e2 = idx % EHALF;
            int t  = idx / EHALF;
            float v = (t0 + t < T) ? hb[t * DD + ebase + e2] : 0.f;
            hs[e2 * HSROW + t] = v;
        }
        __syncthreads();

        #pragma unroll 2
        for (int e = 0; e < EHALF; ++e) {
            float4 w0 = ws4[e * 26 + p];          // cols 4p..4p+3
            float4 w1 = ws4[e * 26 + 13 + p];     // cols 52+4p..52+4p+3
            float4 hA = hs4[e * 33 + 2 * tg];     // rows 8tg..8tg+3
            float4 hB = hs4[e * 33 + 2 * tg + 1]; // rows 8tg+4..8tg+7
            float hv[8] = {hA.x, hA.y, hA.z, hA.w, hB.x, hB.y, hB.z, hB.w};
            #pragma unroll
            for (int i = 0; i < 8; ++i) {
                float hh = hv[i];
                a0[i].x = fmaf(hh, w0.x, a0[i].x);
                a0[i].y = fmaf(hh, w0.y, a0[i].y);
                a0[i].z = fmaf(hh, w0.z, a0[i].z);
                a0[i].w = fmaf(hh, w0.w, a0[i].w);
                a1[i].x = fmaf(hh, w1.x, a1[i].x);
                a1[i].y = fmaf(hh, w1.y, a1[i].y);
                a1[i].z = fmaf(hh, w1.z, a1[i].z);
                a1[i].w = fmaf(hh, w1.w, a1[i].w);
            }
        }
    }

    float bias = bscal[0];
    #pragma unroll
    for (int i = 0; i < 8; ++i) {
        int t = t0 + 8 * tg + i;
        if (t >= T) continue;
        float* grow = g_buf + ((size_t)b * T + t) * GS;
        *(float4*)(grow + 4 * p) = a0[i];                 // cols 0..51
        if (p < 12) {
            *(float4*)(grow + 52 + 4 * p) = a1[i];        // cols 52..99
        } else {
            // p==12 quad1 = cols 100..103 = (content, salience, 0, 0)
            pre_buf[(size_t)b * T + t] = a1[i].x + a1[i].y + apos_buf[t] + bias;
        }
    }
}

// ---------------------------------------------------------------------------
// scan: one warp per batch b; all 32 lanes resident.
// Lane L<25 owns dims 4L..4L+3; lanes 25..31 contribute zero (g scaled by 0).
// g is pre-scaled by 2^18 at load; the lane partial is F2I'd and summed with
// ONE redux.sync.add.s32 (replaces 5 dependent SHFLs), then I2F with the
// 2^-18*log2e scale folded into the sigmoid FMA.
// j==0 peeled (s = 0 -> nov = 0).  Depth-8 branchless prefetch ring.
// ---------------------------------------------------------------------------
__global__ void __launch_bounds__(32, 1) scan_kernel(const float* __restrict__ h,
                                                     float* __restrict__ out,
                                                     int B, int T) {
    int b = blockIdx.x;
    int L = threadIdx.x;
    float gscale = (L < 25) ? 262144.f : 0.f;   // 2^18 * activity mask
    int offE = (L < 25) ? 4 * L : 96;           // clamped, always valid

    const float* gb  = g_buf + (size_t)b * T * GS;
    const float* hbp = h + (size_t)b * T * DD;
    const float* pb  = pre_buf + (size_t)b * T;
    float* ob = out + (size_t)b * T;

    // j = 0: s = 0 -> tanh(s) = 0 -> nov = 0; state not updated.
    {
        float z = pb[0];
        float q = ex2_ap(z * -1.44269504f);
        float p0 = rcp_ap(1.f + q);
        if (L == 0) ob[0] = p0;
    }
    if (T <= 1) return;

    float4 G[8], A[8];
    float PHC[8];

#define LD(JJ, SL) do {                                                    \
        int _jc = ((JJ) < T) ? (JJ) : (T - 1);                             \
        float4 _g = *(const float4*)(gb + (size_t)_jc * GS + offE);        \
        _g.x *= gscale; _g.y *= gscale; _g.z *= gscale; _g.w *= gscale;    \
        G[SL] = _g;                                                        \
        A[SL] = *(const float4*)(hbp + (size_t)_jc * DD + offE);           \
        PHC[SL] = pb[_jc] * -1.44269504f;                                  \
    } while (0)

    LD(1, 1); LD(2, 2); LD(3, 3); LD(4, 4);
    LD(5, 5); LD(6, 6); LD(7, 7); LD(8, 0);

    float sx = 0.f, sy = 0.f, sz = 0.f, sw = 0.f;
    const float RSCALE = 1.44269504f / 262144.f;   // log2e * 2^-18

    #pragma unroll 8
    for (int j = 1; j < T; ++j) {
        int sl = j & 7;
        float4 g = G[sl];
        float4 a = A[sl];
        float phc = PHC[sl];
        LD(j + 8, sl);

        float ux = tanh_ap(sx), uy = tanh_ap(sy), uz = tanh_ap(sz), uw = tanh_ap(sw);
        float m0 = ux * g.x;
        float m1 = uy * g.y;
        m0 = fmaf(uz, g.z, m0);
        m1 = fmaf(uw, g.w, m1);
        int ri = __float2int_rn(m0 + m1);
        int rs = redux_add_i32(ri);
        float novs = __int2float_rn(rs);

        // zz = -(pre - nov)*log2e = nov_scaled*(log2e*2^-18) + phc
        float zz = fmaf(novs, RSCALE, phc);
        float q = ex2_ap(zz);
        float pp = rcp_ap(1.f + q);

        sx = fmaf(a.x, pp, sx);
        sy = fmaf(a.y, pp, sy);
        sz = fmaf(a.z, pp, sz);
        sw = fmaf(a.w, pp, sw);

        if (L == 0) ob[j] = pp;
    }
#undef LD
}

// ---------------------------------------------------------------------------
extern "C" void kernel_launch(void* const* d_in, const int* in_sizes, int n_in,
                              void* d_out, int out_size) {
    const float* h    = (const float*)d_in[0];  // [B,T,D]
    const float* dv   = (const float*)d_in[1];  // [B,1,D]
    const float* w_c  = (const float*)d_in[2];  // [D,1]
    const float* w_s  = (const float*)d_in[3];  // [D,D]
    const float* w_r  = (const float*)d_in[4];  // [D,D]
    const float* pos  = (const float*)d_in[5];  // [3000,D]
    const float* w_ap = (const float*)d_in[6];  // [D,1]
    const float* bsc  = (const float*)d_in[7];  // [1]
    float* out = (float*)d_out;

    int B = in_sizes[1] / DD;
    int T = in_sizes[0] / (B * DD);

    // k0: ds + abs_pos
    int grid0 = B + (T + 127) / 128;
    k0_kernel<<<grid0, 128>>>(dv, w_s, pos, w_ap, B, T);

    // k1: GEMM producing g, pre  (static SMEM 47.2 KB — no attribute calls)
    dim3 grid1((T + TT - 1) / TT, B);
    k1_kernel<<<grid1, 208>>>(h, w_r, w_c, bsc, B, T);

    // scan: one warp per batch
    scan_kernel<<<B, 32>>>(h, out, B, T);
}